// round 13
// baseline (speedup 1.0000x reference)
#include <cuda_runtime.h>
#include <cuda_fp16.h>

#define N_NODES 55296
#define N_EDGES 221184
#define NB      110592   // BATCH * N_NODES

typedef unsigned long long ull;

// ---- dynamic smem layout for msgfused (bytes), 256 threads / 8 warps, 16 edges/warp ----
// [0 .. 65536)        B fragments (4096 x uint4); reused as fp32 stage after mainloop
//                     stage: per warp 32 rows * 36 floats = 4608 B, 8 warps = 36864 B (fits)
// [65536 .. 69632)    eb2 fp32 (1024 float)
// [69632 .. 88064)    feats fp16: per warp 32 rows * 36 halves = 2304 B
// [88064 .. 89088)    idx: per warp 16 src + 16 dst ints = 128 B
#define SM_EB    65536
#define SM_FEAT  69632
#define SM_IDX   88064
#define SM_TOTAL 89088

// Scratch (static device arrays: no allocation at launch time)
__device__ uint4  g_btp4[4096];                          // ew2^T frag-packed [tile nt][lane]
__device__ uint4  g_af[(size_t)(N_EDGES / 16) * 2 * 32]; // A frags: [group][s][lane]
__device__ float  g_hidden[(size_t)NB * 32];
__device__ float  g_agg[(size_t)NB * 32];

__device__ __forceinline__ float sigmoidf_(float x) {
    return __fdividef(1.f, 1.f + __expf(-x));
}
__device__ __forceinline__ void red4(float* p, float a, float b, float c, float d) {
    asm volatile("red.global.add.v4.f32 [%0], {%1,%2,%3,%4};"
                 :: "l"(p), "f"(a), "f"(b), "f"(c), "f"(d) : "memory");
}
__device__ __forceinline__ ull pack2(float lo, float hi) {
    ull v; asm("mov.b64 %0, {%1, %2};" : "=l"(v) : "f"(lo), "f"(hi)); return v;
}
__device__ __forceinline__ float2 unpack2(ull v) {
    float2 f; asm("mov.b64 {%0, %1}, %2;" : "=f"(f.x), "=f"(f.y) : "l"(v)); return f;
}
__device__ __forceinline__ void fma2(ull& d, ull a, ull b) {
    asm("fma.rn.f32x2 %0, %1, %2, %0;" : "+l"(d) : "l"(a), "l"(b));
}
#define MMA_F32(c0,c1,c2,c3,a0,a1,a2,a3,b0,b1) \
    asm volatile("mma.sync.aligned.m16n8k16.row.col.f32.f16.f16.f32 " \
        "{%0,%1,%2,%3}, {%4,%5,%6,%7}, {%8,%9}, {%0,%1,%2,%3};" \
        : "+f"(c0), "+f"(c1), "+f"(c2), "+f"(c3) \
        : "r"(a0), "r"(a1), "r"(a2), "r"(a3), "r"(b0), "r"(b1))

// ---------- node projection: h0 = ReLU(x@pw1+pb1)@pw2+pb2 ; also zero g_agg ----------
__global__ void __launch_bounds__(128) proj_kernel(
    const float* __restrict__ x,
    const float* __restrict__ pw1, const float* __restrict__ pb1,
    const float* __restrict__ pw2, const float* __restrict__ pb2)
{
    __shared__ float s_w1[1024], s_w2[1024], s_b1[32], s_b2[32];
    int t = threadIdx.x;
    for (int i = t; i < 1024; i += 128) { s_w1[i] = pw1[i]; s_w2[i] = pw2[i]; }
    if (t < 32) { s_b1[t] = pb1[t]; s_b2[t] = pb2[t]; }
    __syncthreads();

    int idx = blockIdx.x * 128 + t;

    float4 z = make_float4(0.f, 0.f, 0.f, 0.f);
    float4* zp = (float4*)(g_agg + (size_t)idx * 32);
    #pragma unroll
    for (int j = 0; j < 8; j++) zp[j] = z;

    float v[32];
    const float4* xp = (const float4*)(x + (size_t)idx * 32);
    #pragma unroll
    for (int i = 0; i < 8; i++) {
        float4 xv = xp[i];
        v[4*i+0] = xv.x; v[4*i+1] = xv.y; v[4*i+2] = xv.z; v[4*i+3] = xv.w;
    }
    float4 acc[8];
    #pragma unroll
    for (int j = 0; j < 8; j++) acc[j] = ((const float4*)s_b1)[j];
    #pragma unroll
    for (int c = 0; c < 32; c++) {
        float xv = v[c];
        #pragma unroll
        for (int j = 0; j < 8; j++) {
            float4 w = ((const float4*)s_w1)[c*8 + j];
            acc[j].x = fmaf(xv, w.x, acc[j].x);
            acc[j].y = fmaf(xv, w.y, acc[j].y);
            acc[j].z = fmaf(xv, w.z, acc[j].z);
            acc[j].w = fmaf(xv, w.w, acc[j].w);
        }
    }
    #pragma unroll
    for (int j = 0; j < 8; j++) {
        v[4*j+0] = fmaxf(acc[j].x, 0.f);
        v[4*j+1] = fmaxf(acc[j].y, 0.f);
        v[4*j+2] = fmaxf(acc[j].z, 0.f);
        v[4*j+3] = fmaxf(acc[j].w, 0.f);
    }
    #pragma unroll
    for (int j = 0; j < 8; j++) acc[j] = ((const float4*)s_b2)[j];
    #pragma unroll
    for (int c = 0; c < 32; c++) {
        float xv = v[c];
        #pragma unroll
        for (int j = 0; j < 8; j++) {
            float4 w = ((const float4*)s_w2)[c*8 + j];
            acc[j].x = fmaf(xv, w.x, acc[j].x);
            acc[j].y = fmaf(xv, w.y, acc[j].y);
            acc[j].z = fmaf(xv, w.z, acc[j].z);
            acc[j].w = fmaf(xv, w.w, acc[j].w);
        }
    }
    float4* op = (float4*)(g_hidden + (size_t)idx * 32);
    #pragma unroll
    for (int j = 0; j < 8; j++) op[j] = acc[j];
}

// ---------- prep B: frag-pack ew2^T fp16 ----------
__global__ void prep_b_kernel(const float* __restrict__ ew2)
{
    int idx = blockIdx.x * 256 + threadIdx.x;   // [0, 4096)
    int nt = idx >> 5, lane = idx & 31;
    int g = lane >> 2, tg = lane & 3;
    int n = nt * 8 + g;
    int k0 = tg * 2;
    __half2 p0 = __floats2half2_rn(ew2[(k0+0)*1024 + n],  ew2[(k0+1)*1024 + n]);
    __half2 p1 = __floats2half2_rn(ew2[(k0+8)*1024 + n],  ew2[(k0+9)*1024 + n]);
    __half2 p2 = __floats2half2_rn(ew2[(k0+16)*1024 + n], ew2[(k0+17)*1024 + n]);
    __half2 p3 = __floats2half2_rn(ew2[(k0+24)*1024 + n], ew2[(k0+25)*1024 + n]);
    uint4 v;
    v.x = *(unsigned*)&p0; v.y = *(unsigned*)&p1;
    v.z = *(unsigned*)&p2; v.w = *(unsigned*)&p3;
    g_btp4[idx] = v;
}

// ---------- prep A: A = ReLU(rel@ew1+eb1) fp16, frag-packed per 16-edge group ----------
__global__ void __launch_bounds__(256) prep_a_kernel(
    const float* __restrict__ rel,
    const float* __restrict__ ew1, const float* __restrict__ eb1)
{
    __shared__ float  s_w1[128], s_be[32];
    __shared__ __half s_ae[256][34];
    int t = threadIdx.x;
    if (t < 128) s_w1[t] = ew1[t];
    if (t >= 128 && t < 160) s_be[t - 128] = eb1[t - 128];
    __syncthreads();

    int e = blockIdx.x * 256 + t;
    float4 rp = __ldg((const float4*)rel + e);
    #pragma unroll
    for (int k = 0; k < 32; k++) {
        float a = s_be[k];
        a = fmaf(rp.x, s_w1[k],      a);
        a = fmaf(rp.y, s_w1[32 + k], a);
        a = fmaf(rp.z, s_w1[64 + k], a);
        a = fmaf(rp.w, s_w1[96 + k], a);
        s_ae[t][k] = __float2half(fmaxf(a, 0.f));
    }
    __syncthreads();

    int w = t >> 5, lane = t & 31;
    int g = lane >> 2, tg = lane & 3;
    #pragma unroll
    for (int gi = 0; gi < 2; gi++) {
        int grp = w * 2 + gi;
        int eb_ = grp * 16;
        size_t G = (size_t)blockIdx.x * 16 + grp;
        #pragma unroll
        for (int s = 0; s < 2; s++) {
            int k0 = s * 16 + tg * 2;
            uint4 v;
            v.x = *(unsigned*)&s_ae[eb_ + g][k0];
            v.y = *(unsigned*)&s_ae[eb_ + g + 8][k0];
            v.z = *(unsigned*)&s_ae[eb_ + g][k0 + 8];
            v.w = *(unsigned*)&s_ae[eb_ + g + 8][k0 + 8];
            g_af[(G * 2 + s) * 32 + lane] = v;
        }
    }
}

// ---------- fused message pass: We recomputed via f32-accum MMA; 16 edges/warp ----------
// 256 thr / 8 warps; 128 edges per block. Block-resident B (ew2^T frags) in smem.
// eb2 bias is folded in by initializing the MMA accumulators.
__global__ void __launch_bounds__(256, 2) msgfused_kernel(
    const int* __restrict__ esrc, const int* __restrict__ edst,
    const float* __restrict__ eb2)
{
    extern __shared__ char smem[];
    uint4*  s_b4  = (uint4*)smem;
    float*  s_ebf = (float*)(smem + SM_EB);
    int t = threadIdx.x, w = t >> 5, lane = t & 31;
    __half* s_ft  = (__half*)(smem + SM_FEAT + w * 2304);  // [32 rows (e*2+b)][36 halves]
    int*    s_idx = (int*)(smem + SM_IDX + w * 128);       // [16 src][16 dst]
    float*  s_st  = (float*)(smem + w * 4608);             // stage: [32 rows][36 floats]

    // cooperative: B frags + eb2 (fp32; s_ebf[i] = eb2[i] since jt*8+tg*2 == h*32+o)
    #pragma unroll
    for (int i = 0; i < 16; i++) s_b4[t + i * 256] = g_btp4[t + i * 256];
    ((float4*)s_ebf)[t] = __ldg((const float4*)eb2 + t);

    int e0 = blockIdx.x * 128 + w * 16;
    if (lane < 16)      s_idx[lane] = esrc[e0 + lane];
    else                s_idx[lane] = edst[e0 + lane - 16];
    __syncwarp();

    // gather src feats: 32 rows (e*2+b) x 32 h, fp32 -> fp16 smem
    #pragma unroll
    for (int i = 0; i < 8; i++) {
        int u = lane + 32 * i;            // [0,256)
        int r = u >> 3, q = u & 7;        // r = e*2+b, q = float4 chunk
        int e = r >> 1, b = r & 1;
        int src = s_idx[e];
        float4 v = __ldg((const float4*)(g_hidden + ((size_t)b * N_NODES + src) * 32 + q * 4));
        __half2 h01 = __floats2half2_rn(v.x, v.y);
        __half2 h23 = __floats2half2_rn(v.z, v.w);
        *(uint2*)(s_ft + r * 36 + q * 4) = make_uint2(*(unsigned*)&h01, *(unsigned*)&h23);
    }

    // A fragments for this warp's 16-edge tile
    size_t G0 = (size_t)(e0 >> 4);
    uint4 as0 = __ldg(&g_af[(G0 * 2 + 0) * 32 + lane]);
    uint4 as1 = __ldg(&g_af[(G0 * 2 + 1) * 32 + lane]);

    __syncthreads();   // B/eb visible; feats (warp-local) done

    int g = lane >> 2, tg = lane & 3;
    // acc2[ei][b][m]: edge = g + ei*8, output pair o = {m*8+tg*2, +1}
    ull acc2[2][2][4];
    #pragma unroll
    for (int ei = 0; ei < 2; ei++)
        #pragma unroll
        for (int b = 0; b < 2; b++)
            #pragma unroll
            for (int m = 0; m < 4; m++) acc2[ei][b][m] = 0ull;

    for (int j = 0; j < 8; j++) {          // h = j*4 + p*2 + hl
        #pragma unroll
        for (int p = 0; p < 2; p++) {
            // broadcast feature packs for this h-pair (hoisted over 8 tiles)
            ull fp[2][2][2];   // [ei][b][hl], value duplicated in both halves
            #pragma unroll
            for (int ei = 0; ei < 2; ei++) {
                int e = g + ei * 8;
                #pragma unroll
                for (int b = 0; b < 2; b++) {
                    __half2 hp = *(__half2*)(s_ft + (e * 2 + b) * 36 + j * 4 + p * 2);
                    float2 ff = __half22float2(hp);
                    fp[ei][b][0] = pack2(ff.x, ff.x);
                    fp[ei][b][1] = pack2(ff.y, ff.y);
                }
            }
            #pragma unroll
            for (int nn = 0; nn < 8; nn++) {
                int jt = j * 16 + p * 8 + nn;      // 8-col tile: h = jt>>2, m = jt&3
                uint4 B = s_b4[jt * 32 + lane];
                float2 ebp = *(float2*)(s_ebf + jt * 8 + tg * 2);
                // We chunk in f32, bias pre-loaded into accumulators
                float c0 = ebp.x, c1 = ebp.y, c2 = ebp.x, c3 = ebp.y;
                MMA_F32(c0, c1, c2, c3, as0.x, as0.y, as0.z, as0.w, B.x, B.y);
                MMA_F32(c0, c1, c2, c3, as1.x, as1.y, as1.z, as1.w, B.z, B.w);
                ull v0p = pack2(c0, c1);           // edge g
                ull v1p = pack2(c2, c3);           // edge g+8
                const int hl = nn >> 2;
                const int m = nn & 3;
                fma2(acc2[0][0][m], fp[0][0][hl], v0p);
                fma2(acc2[0][1][m], fp[0][1][hl], v0p);
                fma2(acc2[1][0][m], fp[1][0][hl], v1p);
                fma2(acc2[1][1][m], fp[1][1][hl], v1p);
            }
        }
    }
    __syncthreads();   // everyone done reading s_b4/s_ebf -> reuse as stage

    // stage acc as [row = e*2+b][o] fp32
    #pragma unroll
    for (int ei = 0; ei < 2; ei++) {
        int e = g + ei * 8;
        #pragma unroll
        for (int b = 0; b < 2; b++) {
            #pragma unroll
            for (int m = 0; m < 4; m++) {
                float2 pr = unpack2(acc2[ei][b][m]);
                *(float2*)(s_st + (e * 2 + b) * 36 + m * 8 + tg * 2) = pr;
            }
        }
    }
    __syncwarp();

    // coalesced scatter via red.v4
    #pragma unroll
    for (int i = 0; i < 8; i++) {
        int u = lane + 32 * i;            // [0,256)
        int r = u >> 3, q = u & 7;
        int e = r >> 1, b = r & 1;
        float4 v = *(float4*)(s_st + r * 36 + q * 4);
        int dst = s_idx[16 + e];
        red4(g_agg + ((size_t)b * N_NODES + dst) * 32 + q * 4, v.x, v.y, v.z, v.w);
    }
}

// ---------- GRU via tensor cores (unchanged, validated) ----------
__global__ void __launch_bounds__(256) gru_kernel(
    const float* __restrict__ wih, const float* __restrict__ whh,
    const float* __restrict__ bih, const float* __restrict__ bhh,
    const float* __restrict__ convb,
    float* __restrict__ d_out, int last)
{
    __shared__ __half s_wi[96 * 40];
    __shared__ __half s_wh[96 * 40];
    __shared__ float s_bi[96], s_bh[96], s_cb[32];
    __shared__ __align__(16) char s_buf[8][2880];

    int t = threadIdx.x;
    for (int i = t; i < 3072; i += 256) {
        int n = i >> 5, k = i & 31;
        s_wi[n * 40 + k] = __float2half(wih[i]);
        s_wh[n * 40 + k] = __float2half(whh[i]);
    }
    if (t < 96) { s_bi[t] = bih[t]; s_bh[t] = bhh[t]; }
    if (t >= 128 && t < 160) s_cb[t - 128] = convb[t - 128];
    __syncthreads();

    int w = t >> 5, lane = t & 31;
    int wb = blockIdx.x * 128 + w * 16;
    __half* sx = (__half*)s_buf[w];
    __half* sh = (__half*)(s_buf[w] + 1280);
    float*  so = (float*)s_buf[w];

    int r0 = lane >> 3, c4 = (lane & 7) * 4;
    float4 cb = *(float4*)&s_cb[c4];
    #pragma unroll
    for (int i = 0; i < 4; i++) {
        int row = r0 + i * 4;
        float4 av = *(const float4*)(g_agg + (size_t)(wb + row) * 32 + c4);
        *(__half2*)(sx + row * 40 + c4)     = __floats2half2_rn(fmaxf(av.x + cb.x, 0.f), fmaxf(av.y + cb.y, 0.f));
        *(__half2*)(sx + row * 40 + c4 + 2) = __floats2half2_rn(fmaxf(av.z + cb.z, 0.f), fmaxf(av.w + cb.w, 0.f));
        float4 hv = *(const float4*)(g_hidden + (size_t)(wb + row) * 32 + c4);
        *(__half2*)(sh + row * 40 + c4)     = __floats2half2_rn(hv.x, hv.y);
        *(__half2*)(sh + row * 40 + c4 + 2) = __floats2half2_rn(hv.z, hv.w);
    }
    __syncwarp();

    int g = lane >> 2, tg = lane & 3;
    unsigned af[2][4], hf[2][4];
    #pragma unroll
    for (int s = 0; s < 2; s++) {
        const __half* xr0 = sx + g * 40 + s * 16 + tg * 2;
        const __half* xr1 = sx + (g + 8) * 40 + s * 16 + tg * 2;
        af[s][0] = *(const unsigned*)(xr0);
        af[s][1] = *(const unsigned*)(xr1);
        af[s][2] = *(const unsigned*)(xr0 + 8);
        af[s][3] = *(const unsigned*)(xr1 + 8);
        const __half* hr0 = sh + g * 40 + s * 16 + tg * 2;
        const __half* hr1 = sh + (g + 8) * 40 + s * 16 + tg * 2;
        hf[s][0] = *(const unsigned*)(hr0);
        hf[s][1] = *(const unsigned*)(hr1);
        hf[s][2] = *(const unsigned*)(hr0 + 8);
        hf[s][3] = *(const unsigned*)(hr1 + 8);
    }
    __syncwarp();

    float* outp = last ? d_out : g_hidden;

    #pragma unroll
    for (int cg = 0; cg < 4; cg++) {
        float xr[4] = {0,0,0,0}, xz[4] = {0,0,0,0}, xn[4] = {0,0,0,0};
        float hr[4] = {0,0,0,0}, hz[4] = {0,0,0,0}, hn[4] = {0,0,0,0};
        #pragma unroll
        for (int s = 0; s < 2; s++) {
            const __half* p;
            unsigned b0, b1;
            p = s_wi + (cg * 8 + g) * 40 + s * 16 + tg * 2;
            b0 = *(const unsigned*)p; b1 = *(const unsigned*)(p + 8);
            MMA_F32(xr[0], xr[1], xr[2], xr[3], af[s][0], af[s][1], af[s][2], af[s][3], b0, b1);
            p = s_wi + (32 + cg * 8 + g) * 40 + s * 16 + tg * 2;
            b0 = *(const unsigned*)p; b1 = *(const unsigned*)(p + 8);
            MMA_F32(xz[0], xz[1], xz[2], xz[3], af[s][0], af[s][1], af[s][2], af[s][3], b0, b1);
            p = s_wi + (64 + cg * 8 + g) * 40 + s * 16 + tg * 2;
            b0 = *(const unsigned*)p; b1 = *(const unsigned*)(p + 8);
            MMA_F32(xn[0], xn[1], xn[2], xn[3], af[s][0], af[s][1], af[s][2], af[s][3], b0, b1);
            p = s_wh + (cg * 8 + g) * 40 + s * 16 + tg * 2;
            b0 = *(const unsigned*)p; b1 = *(const unsigned*)(p + 8);
            MMA_F32(hr[0], hr[1], hr[2], hr[3], hf[s][0], hf[s][1], hf[s][2], hf[s][3], b0, b1);
            p = s_wh + (32 + cg * 8 + g) * 40 + s * 16 + tg * 2;
            b0 = *(const unsigned*)p; b1 = *(const unsigned*)(p + 8);
            MMA_F32(hz[0], hz[1], hz[2], hz[3], hf[s][0], hf[s][1], hf[s][2], hf[s][3], b0, b1);
            p = s_wh + (64 + cg * 8 + g) * 40 + s * 16 + tg * 2;
            b0 = *(const unsigned*)p; b1 = *(const unsigned*)(p + 8);
            MMA_F32(hn[0], hn[1], hn[2], hn[3], hf[s][0], hf[s][1], hf[s][2], hf[s][3], b0, b1);
        }
        int u0 = cg * 8 + tg * 2;
        float2 bir = *(float2*)&s_bi[u0],      bhr = *(float2*)&s_bh[u0];
        float2 biz = *(float2*)&s_bi[32 + u0], bhz = *(float2*)&s_bh[32 + u0];
        float2 bin = *(float2*)&s_bi[64 + u0], bhn = *(float2*)&s_bh[64 + u0];
        #pragma unroll
        for (int jp = 0; jp < 2; jp++) {
            int rl = g + jp * 8;
            float2 hold = *(const float2*)(g_hidden + (size_t)(wb + rl) * 32 + u0);
            #pragma unroll
            for (int jj = 0; jj < 2; jj++) {
                int j = jp * 2 + jj;
                float bi_r = jj ? bir.y : bir.x, bh_r = jj ? bhr.y : bhr.x;
                float bi_z = jj ? biz.y : biz.x, bh_z = jj ? bhz.y : bhz.x;
                float bi_n = jj ? bin.y : bin.x, bh_n = jj ? bhn.y : bhn.x;
                float ho = jj ? hold.y : hold.x;
                float rv = sigmoidf_(xr[j] + hr[j] + bi_r + bh_r);
                float zv = sigmoidf_(xz[j] + hz[j] + bi_z + bh_z);
                float nv = tanhf(xn[j] + bi_n + rv * (hn[j] + bh_n));
                so[rl * 36 + u0 + jj] = (1.f - zv) * nv + zv * ho;
            }
        }
    }
    __syncwarp();

    float4 z4 = make_float4(0.f, 0.f, 0.f, 0.f);
    #pragma unroll
    for (int i = 0; i < 4; i++) {
        int row = r0 + i * 4;
        float4 val = *(float4*)(so + row * 36 + c4);
        *(float4*)(outp + (size_t)(wb + row) * 32 + c4) = val;
        *(float4*)(g_agg + (size_t)(wb + row) * 32 + c4) = z4;
    }
}

extern "C" void kernel_launch(void* const* d_in, const int* in_sizes, int n_in,
                              void* d_out, int out_size)
{
    const float* x     = (const float*)d_in[0];
    const float* rel   = (const float*)d_in[1];
    const float* pw1   = (const float*)d_in[2];
    const float* pb1   = (const float*)d_in[3];
    const float* pw2   = (const float*)d_in[4];
    const float* pb2   = (const float*)d_in[5];
    const float* ew1   = (const float*)d_in[6];
    const float* eb1   = (const float*)d_in[7];
    const float* ew2   = (const float*)d_in[8];
    const float* eb2   = (const float*)d_in[9];
    const float* convb = (const float*)d_in[10];
    const float* wih   = (const float*)d_in[11];
    const float* whh   = (const float*)d_in[12];
    const float* bih   = (const float*)d_in[13];
    const float* bhh   = (const float*)d_in[14];
    const int*   esrc  = (const int*)d_in[15];
    const int*   edst  = (const int*)d_in[16];
    float* out = (float*)d_out;

    cudaFuncSetAttribute(msgfused_kernel,
                         cudaFuncAttributeMaxDynamicSharedMemorySize, SM_TOTAL);

    proj_kernel<<<NB / 128, 128>>>(x, pw1, pb1, pw2, pb2);
    prep_b_kernel<<<4096 / 256, 256>>>(ew2);
    prep_a_kernel<<<N_EDGES / 256, 256>>>(rel, ew1, eb1);

    for (int s = 0; s < 3; s++) {
        msgfused_kernel<<<N_EDGES / 128, 256, SM_TOTAL>>>(esrc, edst, eb2);
        gru_kernel<<<NB / 128, 256>>>(wih, whh, bih, bhh, convb, out, s == 2 ? 1 : 0);
    }
}

// round 15
// speedup vs baseline: 1.0417x; 1.0417x over previous
#include <cuda_runtime.h>
#include <cuda_fp16.h>

#define N_NODES 55296
#define N_EDGES 221184
#define NB      110592   // BATCH * N_NODES

typedef unsigned long long ull;

// ---- dynamic smem layout for msgfused (bytes), 256 threads / 8 warps, 16 edges/warp ----
// [0 .. 65536)        B fragments (4096 x uint4); reused as fp32 stage after mainloop
//                     stage: per warp 32 rows * 36 floats = 4608 B, 8 warps = 36864 B (fits)
// [65536 .. 67584)    eb2 fragments (128 x uint4)
// [67584 .. 86016)    feats fp16: per warp 32 rows * 36 halves = 2304 B
// [86016 .. 87040)    idx: per warp 16 src + 16 dst ints = 128 B
#define SM_EB    65536
#define SM_FEAT  67584
#define SM_IDX   86016
#define SM_TOTAL 87040

// Scratch (static device arrays: no allocation at launch time)
__device__ uint4  g_btp4[4096];                          // ew2^T frag-packed [tile nt][lane]
__device__ uint4  g_ebf4[128];                           // eb2 (as 32x32) frag-packed [nt][lane]
__device__ uint4  g_af[(size_t)(N_EDGES / 16) * 2 * 32]; // A frags: [group][s][lane]
__device__ float  g_hidden[(size_t)NB * 32];
__device__ float  g_agg[(size_t)NB * 32];

__device__ __forceinline__ float sigmoidf_(float x) {
    return __fdividef(1.f, 1.f + __expf(-x));
}
__device__ __forceinline__ void red4(float* p, float a, float b, float c, float d) {
    asm volatile("red.global.add.v4.f32 [%0], {%1,%2,%3,%4};"
                 :: "l"(p), "f"(a), "f"(b), "f"(c), "f"(d) : "memory");
}
__device__ __forceinline__ void mma_f16(unsigned& c0, unsigned& c1,
    unsigned a0, unsigned a1, unsigned a2, unsigned a3, unsigned b0, unsigned b1) {
    asm volatile("mma.sync.aligned.m16n8k16.row.col.f16.f16.f16.f16 "
        "{%0,%1}, {%2,%3,%4,%5}, {%6,%7}, {%0,%1};"
        : "+r"(c0), "+r"(c1)
        : "r"(a0), "r"(a1), "r"(a2), "r"(a3), "r"(b0), "r"(b1));
}
#define MMA_F32(c0,c1,c2,c3,a0,a1,a2,a3,b0,b1) \
    asm volatile("mma.sync.aligned.m16n8k16.row.col.f32.f16.f16.f32 " \
        "{%0,%1,%2,%3}, {%4,%5,%6,%7}, {%8,%9}, {%0,%1,%2,%3};" \
        : "+f"(c0), "+f"(c1), "+f"(c2), "+f"(c3) \
        : "r"(a0), "r"(a1), "r"(a2), "r"(a3), "r"(b0), "r"(b1))

// ---------- node projection: h0 = ReLU(x@pw1+pb1)@pw2+pb2 ; also zero g_agg ----------
__global__ void __launch_bounds__(128) proj_kernel(
    const float* __restrict__ x,
    const float* __restrict__ pw1, const float* __restrict__ pb1,
    const float* __restrict__ pw2, const float* __restrict__ pb2)
{
    __shared__ float s_w1[1024], s_w2[1024], s_b1[32], s_b2[32];
    int t = threadIdx.x;
    for (int i = t; i < 1024; i += 128) { s_w1[i] = pw1[i]; s_w2[i] = pw2[i]; }
    if (t < 32) { s_b1[t] = pb1[t]; s_b2[t] = pb2[t]; }
    __syncthreads();

    int idx = blockIdx.x * 128 + t;

    float4 z = make_float4(0.f, 0.f, 0.f, 0.f);
    float4* zp = (float4*)(g_agg + (size_t)idx * 32);
    #pragma unroll
    for (int j = 0; j < 8; j++) zp[j] = z;

    float v[32];
    const float4* xp = (const float4*)(x + (size_t)idx * 32);
    #pragma unroll
    for (int i = 0; i < 8; i++) {
        float4 xv = xp[i];
        v[4*i+0] = xv.x; v[4*i+1] = xv.y; v[4*i+2] = xv.z; v[4*i+3] = xv.w;
    }
    float4 acc[8];
    #pragma unroll
    for (int j = 0; j < 8; j++) acc[j] = ((const float4*)s_b1)[j];
    #pragma unroll
    for (int c = 0; c < 32; c++) {
        float xv = v[c];
        #pragma unroll
        for (int j = 0; j < 8; j++) {
            float4 w = ((const float4*)s_w1)[c*8 + j];
            acc[j].x = fmaf(xv, w.x, acc[j].x);
            acc[j].y = fmaf(xv, w.y, acc[j].y);
            acc[j].z = fmaf(xv, w.z, acc[j].z);
            acc[j].w = fmaf(xv, w.w, acc[j].w);
        }
    }
    #pragma unroll
    for (int j = 0; j < 8; j++) {
        v[4*j+0] = fmaxf(acc[j].x, 0.f);
        v[4*j+1] = fmaxf(acc[j].y, 0.f);
        v[4*j+2] = fmaxf(acc[j].z, 0.f);
        v[4*j+3] = fmaxf(acc[j].w, 0.f);
    }
    #pragma unroll
    for (int j = 0; j < 8; j++) acc[j] = ((const float4*)s_b2)[j];
    #pragma unroll
    for (int c = 0; c < 32; c++) {
        float xv = v[c];
        #pragma unroll
        for (int j = 0; j < 8; j++) {
            float4 w = ((const float4*)s_w2)[c*8 + j];
            acc[j].x = fmaf(xv, w.x, acc[j].x);
            acc[j].y = fmaf(xv, w.y, acc[j].y);
            acc[j].z = fmaf(xv, w.z, acc[j].z);
            acc[j].w = fmaf(xv, w.w, acc[j].w);
        }
    }
    float4* op = (float4*)(g_hidden + (size_t)idx * 32);
    #pragma unroll
    for (int j = 0; j < 8; j++) op[j] = acc[j];
}

// ---------- prep B: frag-pack ew2^T fp16 + eb2 (32x32) frags ----------
__global__ void prep_b_kernel(const float* __restrict__ ew2, const float* __restrict__ eb2)
{
    int idx = blockIdx.x * 256 + threadIdx.x;   // [0, 4096)
    int nt = idx >> 5, lane = idx & 31;
    int g = lane >> 2, tg = lane & 3;
    int n = nt * 8 + g;
    int k0 = tg * 2;
    __half2 p0 = __floats2half2_rn(ew2[(k0+0)*1024 + n],  ew2[(k0+1)*1024 + n]);
    __half2 p1 = __floats2half2_rn(ew2[(k0+8)*1024 + n],  ew2[(k0+9)*1024 + n]);
    __half2 p2 = __floats2half2_rn(ew2[(k0+16)*1024 + n], ew2[(k0+17)*1024 + n]);
    __half2 p3 = __floats2half2_rn(ew2[(k0+24)*1024 + n], ew2[(k0+25)*1024 + n]);
    uint4 v;
    v.x = *(unsigned*)&p0; v.y = *(unsigned*)&p1;
    v.z = *(unsigned*)&p2; v.w = *(unsigned*)&p3;
    g_btp4[idx] = v;

    if (idx < 128) {
        // eb2 viewed as [32 h][32 o]; B-frag for the ebGEMM (n = o, k = h)
        int nt2 = idx >> 5;                    // 0..3
        int n2 = nt2 * 8 + g;                  // o column
        __half2 q0 = __floats2half2_rn(eb2[(k0+0)*32 + n2],  eb2[(k0+1)*32 + n2]);
        __half2 q1 = __floats2half2_rn(eb2[(k0+8)*32 + n2],  eb2[(k0+9)*32 + n2]);
        __half2 q2 = __floats2half2_rn(eb2[(k0+16)*32 + n2], eb2[(k0+17)*32 + n2]);
        __half2 q3 = __floats2half2_rn(eb2[(k0+24)*32 + n2], eb2[(k0+25)*32 + n2]);
        uint4 e4;
        e4.x = *(unsigned*)&q0; e4.y = *(unsigned*)&q1;
        e4.z = *(unsigned*)&q2; e4.w = *(unsigned*)&q3;
        g_ebf4[idx] = e4;
    }
}

// ---------- prep A: A = ReLU(rel@ew1+eb1) fp16, frag-packed per 16-edge group ----------
__global__ void __launch_bounds__(256) prep_a_kernel(
    const float* __restrict__ rel,
    const float* __restrict__ ew1, const float* __restrict__ eb1)
{
    __shared__ float  s_w1[128], s_be[32];
    __shared__ __half s_ae[256][34];
    int t = threadIdx.x;
    if (t < 128) s_w1[t] = ew1[t];
    if (t >= 128 && t < 160) s_be[t - 128] = eb1[t - 128];
    __syncthreads();

    int e = blockIdx.x * 256 + t;
    float4 rp = __ldg((const float4*)rel + e);
    #pragma unroll
    for (int k = 0; k < 32; k++) {
        float a = s_be[k];
        a = fmaf(rp.x, s_w1[k],      a);
        a = fmaf(rp.y, s_w1[32 + k], a);
        a = fmaf(rp.z, s_w1[64 + k], a);
        a = fmaf(rp.w, s_w1[96 + k], a);
        s_ae[t][k] = __float2half(fmaxf(a, 0.f));
    }
    __syncthreads();

    int w = t >> 5, lane = t & 31;
    int g = lane >> 2, tg = lane & 3;
    #pragma unroll
    for (int gi = 0; gi < 2; gi++) {
        int grp = w * 2 + gi;
        int eb_ = grp * 16;
        size_t G = (size_t)blockIdx.x * 16 + grp;
        #pragma unroll
        for (int s = 0; s < 2; s++) {
            int k0 = s * 16 + tg * 2;
            uint4 v;
            v.x = *(unsigned*)&s_ae[eb_ + g][k0];
            v.y = *(unsigned*)&s_ae[eb_ + g + 8][k0];
            v.z = *(unsigned*)&s_ae[eb_ + g][k0 + 8];
            v.w = *(unsigned*)&s_ae[eb_ + g + 8][k0 + 8];
            g_af[(G * 2 + s) * 32 + lane] = v;
        }
    }
}

// ---------- fused message pass: We recomputed via f16 MMA; HFMA2 contraction ----------
// 256 thr / 8 warps; 128 edges per block. Block-resident B (ew2^T frags) in smem.
// eb2 contribution computed once per warp as a small GEMM (feats @ eb2).
__global__ void __launch_bounds__(256, 2) msgfused_kernel(
    const int* __restrict__ esrc, const int* __restrict__ edst)
{
    extern __shared__ char smem[];
    uint4* s_b4 = (uint4*)smem;
    uint4* s_e4 = (uint4*)(smem + SM_EB);
    int t = threadIdx.x, w = t >> 5, lane = t & 31;
    __half* s_ft  = (__half*)(smem + SM_FEAT + w * 2304);  // [32 rows (e*2+b)][36 halves]
    int*    s_idx = (int*)(smem + SM_IDX + w * 128);       // [16 src][16 dst]
    float*  s_st  = (float*)(smem + w * 4608);             // stage: [32 rows][36 floats]

    // cooperative: B frags + eb2 frags
    #pragma unroll
    for (int i = 0; i < 16; i++) s_b4[t + i * 256] = g_btp4[t + i * 256];
    if (t < 128) s_e4[t] = g_ebf4[t];

    int e0 = blockIdx.x * 128 + w * 16;
    if (lane < 16)      s_idx[lane] = esrc[e0 + lane];
    else                s_idx[lane] = edst[e0 + lane - 16];
    __syncwarp();

    // gather src feats: 32 rows (e*2+b) x 32 h, fp32 -> fp16 smem
    #pragma unroll
    for (int i = 0; i < 8; i++) {
        int u = lane + 32 * i;            // [0,256)
        int r = u >> 3, q = u & 7;        // r = e*2+b, q = float4 chunk
        int e = r >> 1, b = r & 1;
        int src = s_idx[e];
        float4 v = __ldg((const float4*)(g_hidden + ((size_t)b * N_NODES + src) * 32 + q * 4));
        __half2 h01 = __floats2half2_rn(v.x, v.y);
        __half2 h23 = __floats2half2_rn(v.z, v.w);
        *(uint2*)(s_ft + r * 36 + q * 4) = make_uint2(*(unsigned*)&h01, *(unsigned*)&h23);
    }

    // A fragments for this warp's 16-edge tile
    size_t G0 = (size_t)(e0 >> 4);
    uint4 as0 = __ldg(&g_af[(G0 * 2 + 0) * 32 + lane]);
    uint4 as1 = __ldg(&g_af[(G0 * 2 + 1) * 32 + lane]);

    __syncthreads();   // B/eb visible; feats (warp-local) done

    int g = lane >> 2, tg = lane & 3;
    // acc2h[ei][b][m]: edge = g + ei*8, output pair o = {m*8+tg*2, +1}, half2 accum
    __half2 acc2h[2][2][4];
    #pragma unroll
    for (int ei = 0; ei < 2; ei++)
        #pragma unroll
        for (int b = 0; b < 2; b++)
            #pragma unroll
            for (int m = 0; m < 4; m++) acc2h[ei][b][m] = __floats2half2_rn(0.f, 0.f);

    for (int j = 0; j < 8; j++) {          // h = j*4 + p*2 + hl
        #pragma unroll
        for (int p = 0; p < 2; p++) {
            // broadcast feature half2 packs for this h-pair (lo/hi duplicated)
            __half2 flo[2][2], fhi[2][2];
            #pragma unroll
            for (int ei = 0; ei < 2; ei++) {
                int e = g + ei * 8;
                #pragma unroll
                for (int b = 0; b < 2; b++) {
                    __half2 ff = *(__half2*)(s_ft + (e * 2 + b) * 36 + j * 4 + p * 2);
                    flo[ei][b] = __low2half2(ff);
                    fhi[ei][b] = __high2half2(ff);
                }
            }
            #pragma unroll
            for (int nn = 0; nn < 8; nn++) {
                int jt = j * 16 + p * 8 + nn;      // 8-col tile: h = jt>>2, m = jt&3
                uint4 B = s_b4[jt * 32 + lane];
                unsigned hc0 = 0u, hc1 = 0u;
                mma_f16(hc0, hc1, as0.x, as0.y, as0.z, as0.w, B.x, B.y);
                mma_f16(hc0, hc1, as1.x, as1.y, as1.z, as1.w, B.z, B.w);
                __half2 v0 = *(__half2*)&hc0;      // edge g,   outputs (o, o+1)
                __half2 v1 = *(__half2*)&hc1;      // edge g+8
                const int hl = nn >> 2;
                const int m = nn & 3;
                acc2h[0][0][m] = __hfma2(hl ? fhi[0][0] : flo[0][0], v0, acc2h[0][0][m]);
                acc2h[0][1][m] = __hfma2(hl ? fhi[0][1] : flo[0][1], v0, acc2h[0][1][m]);
                acc2h[1][0][m] = __hfma2(hl ? fhi[1][0] : flo[1][0], v1, acc2h[1][0][m]);
                acc2h[1][1][m] = __hfma2(hl ? fhi[1][1] : flo[1][1], v1, acc2h[1][1][m]);
            }
        }
    }
    __syncthreads();   // everyone done reading s_b4 -> reuse as stage

    // ebGEMM: msg_eb[row][o] = sum_h feats[row][h] * eb2[h][o]  (f32 accum, exact-ish)
    #pragma unroll
    for (int mt = 0; mt < 2; mt++) {
        unsigned fa[2][4];
        #pragma unroll
        for (int s = 0; s < 2; s++) {
            const __half* base = s_ft + mt * 16 * 36 + s * 16 + tg * 2;
            fa[s][0] = *(const unsigned*)(base + g * 36);
            fa[s][1] = *(const unsigned*)(base + (g + 8) * 36);
            fa[s][2] = *(const unsigned*)(base + g * 36 + 8);
            fa[s][3] = *(const unsigned*)(base + (g + 8) * 36 + 8);
        }
        #pragma unroll
        for (int nt = 0; nt < 4; nt++) {
            uint4 E = s_e4[nt * 32 + lane];
            float c0 = 0.f, c1 = 0.f, c2 = 0.f, c3 = 0.f;
            MMA_F32(c0, c1, c2, c3, fa[0][0], fa[0][1], fa[0][2], fa[0][3], E.x, E.y);
            MMA_F32(c0, c1, c2, c3, fa[1][0], fa[1][1], fa[1][2], fa[1][3], E.z, E.w);
            *(float2*)(s_st + (mt * 16 + g) * 36 + nt * 8 + tg * 2)     = make_float2(c0, c1);
            *(float2*)(s_st + (mt * 16 + g + 8) * 36 + nt * 8 + tg * 2) = make_float2(c2, c3);
        }
    }
    __syncwarp();

    // merge half2 accumulators into stage (read-add-write)
    #pragma unroll
    for (int ei = 0; ei < 2; ei++) {
        int e = g + ei * 8;
        #pragma unroll
        for (int b = 0; b < 2; b++) {
            #pragma unroll
            for (int m = 0; m < 4; m++) {
                float* sp = s_st + (e * 2 + b) * 36 + m * 8 + tg * 2;
                float2 cur = *(float2*)sp;
                float2 av = __half22float2(acc2h[ei][b][m]);
                cur.x += av.x; cur.y += av.y;
                *(float2*)sp = cur;
            }
        }
    }
    __syncwarp();

    // coalesced scatter via red.v4
    #pragma unroll
    for (int i = 0; i < 8; i++) {
        int u = lane + 32 * i;            // [0,256)
        int r = u >> 3, q = u & 7;
        int e = r >> 1, b = r & 1;
        float4 v = *(float4*)(s_st + r * 36 + q * 4);
        int dst = s_idx[16 + e];
        red4(g_agg + ((size_t)b * N_NODES + dst) * 32 + q * 4, v.x, v.y, v.z, v.w);
    }
}

// ---------- GRU via tensor cores (unchanged, validated) ----------
__global__ void __launch_bounds__(256) gru_kernel(
    const float* __restrict__ wih, const float* __restrict__ whh,
    const float* __restrict__ bih, const float* __restrict__ bhh,
    const float* __restrict__ convb,
    float* __restrict__ d_out, int last)
{
    __shared__ __half s_wi[96 * 40];
    __shared__ __half s_wh[96 * 40];
    __shared__ float s_bi[96], s_bh[96], s_cb[32];
    __shared__ __align__(16) char s_buf[8][2880];

    int t = threadIdx.x;
    for (int i = t; i < 3072; i += 256) {
        int n = i >> 5, k = i & 31;
        s_wi[n * 40 + k] = __float2half(wih[i]);
        s_wh[n * 40 + k] = __float2half(whh[i]);
    }
    if (t < 96) { s_bi[t] = bih[t]; s_bh[t] = bhh[t]; }
    if (t >= 128 && t < 160) s_cb[t - 128] = convb[t - 128];
    __syncthreads();

    int w = t >> 5, lane = t & 31;
    int wb = blockIdx.x * 128 + w * 16;
    __half* sx = (__half*)s_buf[w];
    __half* sh = (__half*)(s_buf[w] + 1280);
    float*  so = (float*)s_buf[w];

    int r0 = lane >> 3, c4 = (lane & 7) * 4;
    float4 cb = *(float4*)&s_cb[c4];
    #pragma unroll
    for (int i = 0; i < 4; i++) {
        int row = r0 + i * 4;
        float4 av = *(const float4*)(g_agg + (size_t)(wb + row) * 32 + c4);
        *(__half2*)(sx + row * 40 + c4)     = __floats2half2_rn(fmaxf(av.x + cb.x, 0.f), fmaxf(av.y + cb.y, 0.f));
        *(__half2*)(sx + row * 40 + c4 + 2) = __floats2half2_rn(fmaxf(av.z + cb.z, 0.f), fmaxf(av.w + cb.w, 0.f));
        float4 hv = *(const float4*)(g_hidden + (size_t)(wb + row) * 32 + c4);
        *(__half2*)(sh + row * 40 + c4)     = __floats2half2_rn(hv.x, hv.y);
        *(__half2*)(sh + row * 40 + c4 + 2) = __floats2half2_rn(hv.z, hv.w);
    }
    __syncwarp();

    int g = lane >> 2, tg = lane & 3;
    unsigned af[2][4], hf[2][4];
    #pragma unroll
    for (int s = 0; s < 2; s++) {
        const __half* xr0 = sx + g * 40 + s * 16 + tg * 2;
        const __half* xr1 = sx + (g + 8) * 40 + s * 16 + tg * 2;
        af[s][0] = *(const unsigned*)(xr0);
        af[s][1] = *(const unsigned*)(xr1);
        af[s][2] = *(const unsigned*)(xr0 + 8);
        af[s][3] = *(const unsigned*)(xr1 + 8);
        const __half* hr0 = sh + g * 40 + s * 16 + tg * 2;
        const __half* hr1 = sh + (g + 8) * 40 + s * 16 + tg * 2;
        hf[s][0] = *(const unsigned*)(hr0);
        hf[s][1] = *(const unsigned*)(hr1);
        hf[s][2] = *(const unsigned*)(hr0 + 8);
        hf[s][3] = *(const unsigned*)(hr1 + 8);
    }
    __syncwarp();

    float* outp = last ? d_out : g_hidden;

    #pragma unroll
    for (int cg = 0; cg < 4; cg++) {
        float xr[4] = {0,0,0,0}, xz[4] = {0,0,0,0}, xn[4] = {0,0,0,0};
        float hr[4] = {0,0,0,0}, hz[4] = {0,0,0,0}, hn[4] = {0,0,0,0};
        #pragma unroll
        for (int s = 0; s < 2; s++) {
            const __half* p;
            unsigned b0, b1;
            p = s_wi + (cg * 8 + g) * 40 + s * 16 + tg * 2;
            b0 = *(const unsigned*)p; b1 = *(const unsigned*)(p + 8);
            MMA_F32(xr[0], xr[1], xr[2], xr[3], af[s][0], af[s][1], af[s][2], af[s][3], b0, b1);
            p = s_wi + (32 + cg * 8 + g) * 40 + s * 16 + tg * 2;
            b0 = *(const unsigned*)p; b1 = *(const unsigned*)(p + 8);
            MMA_F32(xz[0], xz[1], xz[2], xz[3], af[s][0], af[s][1], af[s][2], af[s][3], b0, b1);
            p = s_wi + (64 + cg * 8 + g) * 40 + s * 16 + tg * 2;
            b0 = *(const unsigned*)p; b1 = *(const unsigned*)(p + 8);
            MMA_F32(xn[0], xn[1], xn[2], xn[3], af[s][0], af[s][1], af[s][2], af[s][3], b0, b1);
            p = s_wh + (cg * 8 + g) * 40 + s * 16 + tg * 2;
            b0 = *(const unsigned*)p; b1 = *(const unsigned*)(p + 8);
            MMA_F32(hr[0], hr[1], hr[2], hr[3], hf[s][0], hf[s][1], hf[s][2], hf[s][3], b0, b1);
            p = s_wh + (32 + cg * 8 + g) * 40 + s * 16 + tg * 2;
            b0 = *(const unsigned*)p; b1 = *(const unsigned*)(p + 8);
            MMA_F32(hz[0], hz[1], hz[2], hz[3], hf[s][0], hf[s][1], hf[s][2], hf[s][3], b0, b1);
            p = s_wh + (64 + cg * 8 + g) * 40 + s * 16 + tg * 2;
            b0 = *(const unsigned*)p; b1 = *(const unsigned*)(p + 8);
            MMA_F32(hn[0], hn[1], hn[2], hn[3], hf[s][0], hf[s][1], hf[s][2], hf[s][3], b0, b1);
        }
        int u0 = cg * 8 + tg * 2;
        float2 bir = *(float2*)&s_bi[u0],      bhr = *(float2*)&s_bh[u0];
        float2 biz = *(float2*)&s_bi[32 + u0], bhz = *(float2*)&s_bh[32 + u0];
        float2 bin = *(float2*)&s_bi[64 + u0], bhn = *(float2*)&s_bh[64 + u0];
        #pragma unroll
        for (int jp = 0; jp < 2; jp++) {
            int rl = g + jp * 8;
            float2 hold = *(const float2*)(g_hidden + (size_t)(wb + rl) * 32 + u0);
            #pragma unroll
            for (int jj = 0; jj < 2; jj++) {
                int j = jp * 2 + jj;
                float bi_r = jj ? bir.y : bir.x, bh_r = jj ? bhr.y : bhr.x;
                float bi_z = jj ? biz.y : biz.x, bh_z = jj ? bhz.y : bhz.x;
                float bi_n = jj ? bin.y : bin.x, bh_n = jj ? bhn.y : bhn.x;
                float ho = jj ? hold.y : hold.x;
                float rv = sigmoidf_(xr[j] + hr[j] + bi_r + bh_r);
                float zv = sigmoidf_(xz[j] + hz[j] + bi_z + bh_z);
                float nv = tanhf(xn[j] + bi_n + rv * (hn[j] + bh_n));
                so[rl * 36 + u0 + jj] = (1.f - zv) * nv + zv * ho;
            }
        }
    }
    __syncwarp();

    float4 z4 = make_float4(0.f, 0.f, 0.f, 0.f);
    #pragma unroll
    for (int i = 0; i < 4; i++) {
        int row = r0 + i * 4;
        float4 val = *(float4*)(so + row * 36 + c4);
        *(float4*)(outp + (size_t)(wb + row) * 32 + c4) = val;
        *(float4*)(g_agg + (size_t)(wb + row) * 32 + c4) = z4;
    }
}

extern "C" void kernel_launch(void* const* d_in, const int* in_sizes, int n_in,
                              void* d_out, int out_size)
{
    const float* x     = (const float*)d_in[0];
    const float* rel   = (const float*)d_in[1];
    const float* pw1   = (const float*)d_in[2];
    const float* pb1   = (const float*)d_in[3];
    const float* pw2   = (const float*)d_in[4];
    const float* pb2   = (const float*)d_in[5];
    const float* ew1   = (const float*)d_in[6];
    const float* eb1   = (const float*)d_in[7];
    const float* ew2   = (const float*)d_in[8];
    const float* eb2   = (const float*)d_in[9];
    const float* convb = (const float*)d_in[10];
    const float* wih   = (const float*)d_in[11];
    const float* whh   = (const float*)d_in[12];
    const float* bih   = (const float*)d_in[13];
    const float* bhh   = (const float*)d_in[14];
    const int*   esrc  = (const int*)d_in[15];
    const int*   edst  = (const int*)d_in[16];
    float* out = (float*)d_out;

    cudaFuncSetAttribute(msgfused_kernel,
                         cudaFuncAttributeMaxDynamicSharedMemorySize, SM_TOTAL);

    proj_kernel<<<NB / 128, 128>>>(x, pw1, pb1, pw2, pb2);
    prep_b_kernel<<<4096 / 256, 256>>>(ew2, eb2);
    prep_a_kernel<<<N_EDGES / 256, 256>>>(rel, ew1, eb1);

    for (int s = 0; s < 3; s++) {
        msgfused_kernel<<<N_EDGES / 128, 256, SM_TOTAL>>>(esrc, edst);
        gru_kernel<<<NB / 128, 256>>>(wih, whh, bih, bhh, convb, out, s == 2 ? 1 : 0);
    }
}